// round 1
// baseline (speedup 1.0000x reference)
#include <cuda_runtime.h>
#include <math.h>

#define BB 8
#define SS 2048
#define EE 1024
#define DD 64

// Scratch for q,k,v projections (device-global: allocation rules forbid cudaMalloc)
__device__ float g_q[BB * SS * DD];
__device__ float g_k[BB * SS * DD];
__device__ float g_v[BB * SS * DD];

// ---------------------------------------------------------------------------
// QKV projection: out[m, n] = sum_e x[m, e] * W[n, e] + b[n]
// M = B*S = 16384, N = 64, K = 1024.
// Tiled SGEMM: BM=64, BN=64, BK=16, 256 threads, 4x4 register microtile.
// blockIdx.y selects q / k / v.
// ---------------------------------------------------------------------------
__global__ void qkv_kernel(const float* __restrict__ x,
                           const float* __restrict__ Wq, const float* __restrict__ bq,
                           const float* __restrict__ Wk, const float* __restrict__ bk,
                           const float* __restrict__ Wv, const float* __restrict__ bv) {
    __shared__ float As[16][65];  // As[k][m]
    __shared__ float Bs[16][65];  // Bs[k][n]

    const int mat = blockIdx.y;
    const float* W    = (mat == 0) ? Wq : (mat == 1) ? Wk : Wv;
    const float* bias = (mat == 0) ? bq : (mat == 1) ? bk : bv;
    float* out        = (mat == 0) ? g_q : (mat == 1) ? g_k : g_v;

    const int m0 = blockIdx.x * 64;
    const int t  = threadIdx.x;           // 0..255
    const int tx = t & 15;                 // 0..15 (n tiles)
    const int ty = t >> 4;                 // 0..15 (m tiles)

    // loader mapping: each thread loads one float4 per tile per matrix
    const int lr = t >> 2;                 // 0..63 (row within tile)
    const int lc = (t & 3) * 4;            // 0,4,8,12 (k offset)

    float acc[4][4] = {};

    for (int k0 = 0; k0 < EE; k0 += 16) {
        float4 a = *reinterpret_cast<const float4*>(&x[(size_t)(m0 + lr) * EE + k0 + lc]);
        As[lc + 0][lr] = a.x; As[lc + 1][lr] = a.y;
        As[lc + 2][lr] = a.z; As[lc + 3][lr] = a.w;
        float4 w = *reinterpret_cast<const float4*>(&W[(size_t)lr * EE + k0 + lc]);
        Bs[lc + 0][lr] = w.x; Bs[lc + 1][lr] = w.y;
        Bs[lc + 2][lr] = w.z; Bs[lc + 3][lr] = w.w;
        __syncthreads();

        #pragma unroll
        for (int k = 0; k < 16; k++) {
            float ar[4], br[4];
            #pragma unroll
            for (int i = 0; i < 4; i++) ar[i] = As[k][ty * 4 + i];
            #pragma unroll
            for (int j = 0; j < 4; j++) br[j] = Bs[k][tx * 4 + j];
            #pragma unroll
            for (int i = 0; i < 4; i++)
                #pragma unroll
                for (int j = 0; j < 4; j++)
                    acc[i][j] = fmaf(ar[i], br[j], acc[i][j]);
        }
        __syncthreads();
    }

    #pragma unroll
    for (int i = 0; i < 4; i++) {
        const int m = m0 + ty * 4 + i;
        #pragma unroll
        for (int j = 0; j < 4; j++) {
            const int n = tx * 4 + j;
            out[(size_t)m * DD + n] = acc[i][j] + bias[n];
        }
    }
}

// ---------------------------------------------------------------------------
// Flash-attention tile kernel.
// Block: 64 queries of one batch. Loop over key tiles of 64.
// 256 threads, 4x4 microtile for both QK^T and PV GEMMs.
// Dynamic smem: Qs(64x65) | Ks(64x65, aliased as P after scores) | Vs(64x65)
// ---------------------------------------------------------------------------
#define SMEM_FLOATS (3 * 64 * 65)
#define SMEM_BYTES  (SMEM_FLOATS * 4)

__global__ void attn_kernel(const int* __restrict__ mask, float* __restrict__ out) {
    extern __shared__ float sm[];
    float* Qs = sm;                  // [64][65]  query tile
    float* Ks = sm + 64 * 65;        // [64][65]  key tile, reused as P tile
    float* Vs = sm + 2 * 64 * 65;    // [64][65]  value tile

    const int b  = blockIdx.y;
    const int q0 = blockIdx.x * 64;
    const int t  = threadIdx.x;
    const int tx = t & 15;           // key-col / d-col tiles
    const int ty = t >> 4;           // query-row tiles

    const float* qptr  = g_q + ((size_t)b * SS + q0) * DD;
    const float* kbase = g_k + (size_t)b * SS * DD;
    const float* vbase = g_v + (size_t)b * SS * DD;
    const int*   mrow  = mask + (size_t)b * SS;

    const int lr = t >> 2;           // 0..63
    const int lc = (t & 3) * 4;      // 0,4,8,12

    // load Q tile (64x64)
    #pragma unroll
    for (int c = lc; c < DD; c += 16) {
        float4 qv = *reinterpret_cast<const float4*>(&qptr[lr * DD + c]);
        Qs[lr * 65 + c + 0] = qv.x; Qs[lr * 65 + c + 1] = qv.y;
        Qs[lr * 65 + c + 2] = qv.z; Qs[lr * 65 + c + 3] = qv.w;
    }

    float o[4][4] = {};
    float m_run[4] = {-INFINITY, -INFINITY, -INFINITY, -INFINITY};
    float l_run[4] = {};

    const float scale = 0.125f;  // 1/sqrt(64)

    for (int k0 = 0; k0 < SS; k0 += 64) {
        __syncthreads();  // prior-iter readers of Ks/Vs done

        // load K,V tiles (64x64 each)
        #pragma unroll
        for (int c = lc; c < DD; c += 16) {
            float4 kv = *reinterpret_cast<const float4*>(&kbase[(size_t)(k0 + lr) * DD + c]);
            Ks[lr * 65 + c + 0] = kv.x; Ks[lr * 65 + c + 1] = kv.y;
            Ks[lr * 65 + c + 2] = kv.z; Ks[lr * 65 + c + 3] = kv.w;
            float4 vv = *reinterpret_cast<const float4*>(&vbase[(size_t)(k0 + lr) * DD + c]);
            Vs[lr * 65 + c + 0] = vv.x; Vs[lr * 65 + c + 1] = vv.y;
            Vs[lr * 65 + c + 2] = vv.z; Vs[lr * 65 + c + 3] = vv.w;
        }
        __syncthreads();

        // scores: s[i][j] = q_row(ty*4+i) . k_row(tx*4+j)
        float s[4][4] = {};
        #pragma unroll
        for (int d = 0; d < DD; d++) {
            float ar[4], br[4];
            #pragma unroll
            for (int i = 0; i < 4; i++) ar[i] = Qs[(ty * 4 + i) * 65 + d];
            #pragma unroll
            for (int j = 0; j < 4; j++) br[j] = Ks[(tx * 4 + j) * 65 + d];
            #pragma unroll
            for (int i = 0; i < 4; i++)
                #pragma unroll
                for (int j = 0; j < 4; j++)
                    s[i][j] = fmaf(ar[i], br[j], s[i][j]);
        }

        // scale + padding mask (mask keys)
        bool km[4];
        #pragma unroll
        for (int j = 0; j < 4; j++) km[j] = (mrow[k0 + tx * 4 + j] != 0);
        #pragma unroll
        for (int i = 0; i < 4; i++)
            #pragma unroll
            for (int j = 0; j < 4; j++)
                s[i][j] = km[j] ? -INFINITY : s[i][j] * scale;

        // row max over 16 lanes sharing ty (lanes are contiguous 16-groups)
        float rmax[4];
        #pragma unroll
        for (int i = 0; i < 4; i++) {
            float v = fmaxf(fmaxf(s[i][0], s[i][1]), fmaxf(s[i][2], s[i][3]));
            #pragma unroll
            for (int off = 8; off >= 1; off >>= 1)
                v = fmaxf(v, __shfl_xor_sync(0xffffffffu, v, off, 16));
            rmax[i] = v;
        }

        float newm[4], fac[4], rsum[4];
        #pragma unroll
        for (int i = 0; i < 4; i++) {
            newm[i] = fmaxf(m_run[i], rmax[i]);
            fac[i]  = (m_run[i] == -INFINITY) ? 0.0f : __expf(m_run[i] - newm[i]);
            rsum[i] = 0.0f;
        }

        // p = exp(s - newm); masked entries exactly 0 (also handles all-masked)
        #pragma unroll
        for (int i = 0; i < 4; i++)
            #pragma unroll
            for (int j = 0; j < 4; j++) {
                float p = (s[i][j] == -INFINITY) ? 0.0f : __expf(s[i][j] - newm[i]);
                s[i][j] = p;
                rsum[i] += p;
            }

        #pragma unroll
        for (int i = 0; i < 4; i++) {
            float v = rsum[i];
            #pragma unroll
            for (int off = 8; off >= 1; off >>= 1)
                v += __shfl_xor_sync(0xffffffffu, v, off, 16);
            l_run[i] = l_run[i] * fac[i] + v;
            m_run[i] = newm[i];
        }

        // rescale running output
        #pragma unroll
        for (int i = 0; i < 4; i++)
            #pragma unroll
            for (int j = 0; j < 4; j++)
                o[i][j] *= fac[i];

        __syncthreads();  // everyone done reading Ks before overwrite as P

        // store P over Ks
        #pragma unroll
        for (int i = 0; i < 4; i++)
            #pragma unroll
            for (int j = 0; j < 4; j++)
                Ks[(ty * 4 + i) * 65 + (tx * 4 + j)] = s[i][j];
        __syncthreads();

        // o += P @ V : o[i][j] += sum_kk P[row][kk] * V[kk][dcol]
        #pragma unroll
        for (int kk = 0; kk < 64; kk++) {
            float pr[4], vr[4];
            #pragma unroll
            for (int i = 0; i < 4; i++) pr[i] = Ks[(ty * 4 + i) * 65 + kk];
            #pragma unroll
            for (int j = 0; j < 4; j++) vr[j] = Vs[kk * 65 + tx * 4 + j];
            #pragma unroll
            for (int i = 0; i < 4; i++)
                #pragma unroll
                for (int j = 0; j < 4; j++)
                    o[i][j] = fmaf(pr[i], vr[j], o[i][j]);
        }
    }

    // epilogue: out[b, q0+row, dcol] = o / l
    #pragma unroll
    for (int i = 0; i < 4; i++) {
        const float inv_l = 1.0f / l_run[i];
        const int q = q0 + ty * 4 + i;
        #pragma unroll
        for (int j = 0; j < 4; j++)
            out[((size_t)b * SS + q) * DD + tx * 4 + j] = o[i][j] * inv_l;
    }
}

// ---------------------------------------------------------------------------
// Launch
// ---------------------------------------------------------------------------
extern "C" void kernel_launch(void* const* d_in, const int* in_sizes, int n_in,
                              void* d_out, int out_size) {
    const float* x  = (const float*)d_in[0];
    const float* Wq = (const float*)d_in[1];
    const float* bq = (const float*)d_in[2];
    const float* Wk = (const float*)d_in[3];
    const float* bk = (const float*)d_in[4];
    const float* Wv = (const float*)d_in[5];
    const float* bv = (const float*)d_in[6];
    const int*   pm = (const int*)d_in[7];   // padding_mask (bool -> int32 assumed)
    float* out = (float*)d_out;

    dim3 g1(BB * SS / 64, 3);
    qkv_kernel<<<g1, 256>>>(x, Wq, bq, Wk, bk, Wv, bv);

    cudaFuncSetAttribute(attn_kernel, cudaFuncAttributeMaxDynamicSharedMemorySize, SMEM_BYTES);
    dim3 g2(SS / 64, BB);
    attn_kernel<<<g2, 256, SMEM_BYTES>>>(pm, out);
}

// round 2
// speedup vs baseline: 1.8108x; 1.8108x over previous
#include <cuda_runtime.h>
#include <cstdint>
#include <math.h>

#define BB 8
#define SS 2048
#define EE 1024
#define DD 64

// q,k,v stored as bf16 hi/lo planes, 2 bf16 packed per u32 (even d in low half)
__device__ unsigned int g_qh[BB * SS * DD / 2];
__device__ unsigned int g_ql[BB * SS * DD / 2];
__device__ unsigned int g_kh[BB * SS * DD / 2];
__device__ unsigned int g_kl[BB * SS * DD / 2];
__device__ unsigned int g_vh[BB * SS * DD / 2];
__device__ unsigned int g_vl[BB * SS * DD / 2];

// ---------------------------------------------------------------------------
// helpers
// ---------------------------------------------------------------------------
__device__ __forceinline__ uint32_t smem_u32(const void* p) {
    return (uint32_t)__cvta_generic_to_shared(p);
}

__device__ __forceinline__ void ldsm_x4(uint32_t addr, uint32_t& r0, uint32_t& r1,
                                        uint32_t& r2, uint32_t& r3) {
    asm volatile("ldmatrix.sync.aligned.m8n8.x4.shared.b16 {%0,%1,%2,%3}, [%4];"
                 : "=r"(r0), "=r"(r1), "=r"(r2), "=r"(r3) : "r"(addr));
}

__device__ __forceinline__ void mma_bf16(float c[4],
                                         uint32_t a0, uint32_t a1, uint32_t a2, uint32_t a3,
                                         uint32_t b0, uint32_t b1) {
    asm volatile("mma.sync.aligned.m16n8k16.row.col.f32.bf16.bf16.f32 "
                 "{%0,%1,%2,%3}, {%4,%5,%6,%7}, {%8,%9}, {%0,%1,%2,%3};"
                 : "+f"(c[0]), "+f"(c[1]), "+f"(c[2]), "+f"(c[3])
                 : "r"(a0), "r"(a1), "r"(a2), "r"(a3), "r"(b0), "r"(b1));
}

// pack (x0 -> low half, x1 -> high half) as bf16x2
__device__ __forceinline__ uint32_t pack2(float x0, float x1) {
    uint32_t h;
    asm("cvt.rn.bf16x2.f32 %0, %1, %2;" : "=r"(h) : "f"(x1), "f"(x0));
    return h;
}

// split pair of f32 into bf16 hi plane + bf16 lo (residual) plane
__device__ __forceinline__ void split_pair(float x0, float x1, uint32_t& hi, uint32_t& lo) {
    hi = pack2(x0, x1);
    float h0 = __uint_as_float(hi << 16);
    float h1 = __uint_as_float(hi & 0xffff0000u);
    lo = pack2(x0 - h0, x1 - h1);
}

// ---------------------------------------------------------------------------
// QKV projection: q/k/v[m,n] = x[m,:] . W[n,:] + b[n]   (M=16384, N=64, K=1024)
// bf16 hi/lo split, 3 MMAs per tile. All three matrices per block.
// Block: 256 threads (8 warps = 4 along M x 2 along N). BM=64, BK=16.
// ---------------------------------------------------------------------------
#define AP 24   // A smem pitch (bf16)
#define WP 24   // W smem pitch (bf16)

__global__ __launch_bounds__(256) void qkv_kernel(
    const float* __restrict__ x,
    const float* __restrict__ Wq, const float* __restrict__ bq,
    const float* __restrict__ Wk, const float* __restrict__ bk,
    const float* __restrict__ Wv, const float* __restrict__ bv)
{
    __shared__ unsigned short Ah[64][AP], Al[64][AP];
    __shared__ unsigned short Wh[3][64][WP], Wl[3][64][WP];

    const int t = threadIdx.x;
    const int warp = t >> 5, lane = t & 31;
    const int wm = warp >> 1;   // m tile: wm*16
    const int wn = warp & 1;    // n tile: wn*32
    const int m0 = blockIdx.x * 64;

    float acc[3][4][4] = {};    // [mat][n-atom][reg]

    // fixed ldmatrix lane addressing
    const int arow = wm * 16 + (lane & 15);
    const int acol = (lane >> 4) * 8;
    const int brow = (lane & 7) + ((lane >> 4) << 3);
    const int bcol = ((lane >> 3) & 1) * 8;

    const uint32_t a_addr_h = smem_u32(&Ah[arow][acol]);
    const uint32_t a_addr_l = smem_u32(&Al[arow][acol]);

    for (int k0 = 0; k0 < EE; k0 += 16) {
        // --- stage A (x tile 64x16 f32), split to bf16 hi/lo ---
        {
            int idx = t * 4;                 // 0..1023
            int r = idx >> 4, c = idx & 15;  // c in {0,4,8,12}
            float4 v = *reinterpret_cast<const float4*>(&x[(size_t)(m0 + r) * EE + k0 + c]);
            uint32_t h0, l0, h1, l1;
            split_pair(v.x, v.y, h0, l0);
            split_pair(v.z, v.w, h1, l1);
            *(uint32_t*)&Ah[r][c]     = h0;  *(uint32_t*)&Al[r][c]     = l0;
            *(uint32_t*)&Ah[r][c + 2] = h1;  *(uint32_t*)&Al[r][c + 2] = l1;
        }
        // --- stage W tiles (3 x 64x16) ---
        #pragma unroll
        for (int i = 0; i < 3; i++) {
            const float* Wp = (i == 0) ? Wq : (i == 1) ? Wk : Wv;
            int r = t >> 2, c = (t & 3) * 4;
            float4 v = *reinterpret_cast<const float4*>(&Wp[(size_t)r * EE + k0 + c]);
            uint32_t h0, l0, h1, l1;
            split_pair(v.x, v.y, h0, l0);
            split_pair(v.z, v.w, h1, l1);
            *(uint32_t*)&Wh[i][r][c]     = h0;  *(uint32_t*)&Wl[i][r][c]     = l0;
            *(uint32_t*)&Wh[i][r][c + 2] = h1;  *(uint32_t*)&Wl[i][r][c + 2] = l1;
        }
        __syncthreads();

        uint32_t ah[4], al[4];
        ldsm_x4(a_addr_h, ah[0], ah[1], ah[2], ah[3]);
        ldsm_x4(a_addr_l, al[0], al[1], al[2], al[3]);

        #pragma unroll
        for (int mat = 0; mat < 3; mat++) {
            #pragma unroll
            for (int pr = 0; pr < 2; pr++) {  // each pair = 2 n-atoms
                uint32_t bh0, bh1, bh2, bh3, bl0, bl1, bl2, bl3;
                ldsm_x4(smem_u32(&Wh[mat][wn * 32 + pr * 16 + brow][bcol]), bh0, bh1, bh2, bh3);
                ldsm_x4(smem_u32(&Wl[mat][wn * 32 + pr * 16 + brow][bcol]), bl0, bl1, bl2, bl3);
                float* c0 = acc[mat][pr * 2];
                float* c1 = acc[mat][pr * 2 + 1];
                mma_bf16(c0, ah[0], ah[1], ah[2], ah[3], bh0, bh1);
                mma_bf16(c0, ah[0], ah[1], ah[2], ah[3], bl0, bl1);
                mma_bf16(c0, al[0], al[1], al[2], al[3], bh0, bh1);
                mma_bf16(c1, ah[0], ah[1], ah[2], ah[3], bh2, bh3);
                mma_bf16(c1, ah[0], ah[1], ah[2], ah[3], bl2, bl3);
                mma_bf16(c1, al[0], al[1], al[2], al[3], bh2, bh3);
            }
        }
        __syncthreads();
    }

    // --- epilogue: add bias, split to hi/lo planes, store ---
    #pragma unroll
    for (int mat = 0; mat < 3; mat++) {
        const float* bias = (mat == 0) ? bq : (mat == 1) ? bk : bv;
        unsigned int* gh = (mat == 0) ? g_qh : (mat == 1) ? g_kh : g_vh;
        unsigned int* gl = (mat == 0) ? g_ql : (mat == 1) ? g_kl : g_vl;
        #pragma unroll
        for (int na = 0; na < 4; na++) {
            int col  = wn * 32 + na * 8 + (lane & 3) * 2;
            int row0 = m0 + wm * 16 + (lane >> 2);
            float b0 = bias[col], b1 = bias[col + 1];
            float c0 = acc[mat][na][0] + b0, c1 = acc[mat][na][1] + b1;
            float c2 = acc[mat][na][2] + b0, c3 = acc[mat][na][3] + b1;
            uint32_t h, l;
            split_pair(c0, c1, h, l);
            gh[(size_t)row0 * 32 + col / 2] = h;
            gl[(size_t)row0 * 32 + col / 2] = l;
            split_pair(c2, c3, h, l);
            gh[(size_t)(row0 + 8) * 32 + col / 2] = h;
            gl[(size_t)(row0 + 8) * 32 + col / 2] = l;
        }
    }
}

// ---------------------------------------------------------------------------
// Flash attention with mma. Block: 128 threads (4 warps), q-tile 64 (16 q/warp),
// key-tile 64. Online softmax in registers; P repacked to bf16 frags in regs.
// ---------------------------------------------------------------------------
#define KP 72   // smem pitch (bf16)

__global__ __launch_bounds__(128) void attn_kernel(const int* __restrict__ mask,
                                                   float* __restrict__ out)
{
    __shared__ unsigned short Kh[64][KP], Kl[64][KP];   // keys x d (also stages Q)
    __shared__ unsigned short Vh[64][KP], Vl[64][KP];   // V^T: d x keys
    __shared__ float ms[64];                            // additive mask (0 or -inf)

    const int t = threadIdx.x, warp = t >> 5, lane = t & 31;
    const int b = blockIdx.y, q0 = blockIdx.x * 64;

    // --- stage Q tile into Kh/Kl, load Q fragments into registers ---
    #pragma unroll
    for (int i = 0; i < 16; i++) {
        int idx = t + i * 128;           // 0..2047
        int r = idx >> 5, cu = idx & 31;
        size_t g = ((size_t)b * SS + q0 + r) * 32 + cu;
        *(uint32_t*)&Kh[r][cu * 2] = g_qh[g];
        *(uint32_t*)&Kl[r][cu * 2] = g_ql[g];
    }
    __syncthreads();

    uint32_t qh[4][4], ql[4][4];
    {
        const int arow = warp * 16 + (lane & 15);
        const int acol = (lane >> 4) * 8;
        #pragma unroll
        for (int ks = 0; ks < 4; ks++) {
            ldsm_x4(smem_u32(&Kh[arow][ks * 16 + acol]), qh[ks][0], qh[ks][1], qh[ks][2], qh[ks][3]);
            ldsm_x4(smem_u32(&Kl[arow][ks * 16 + acol]), ql[ks][0], ql[ks][1], ql[ks][2], ql[ks][3]);
        }
    }

    float O[8][4] = {};
    float m0r = -INFINITY, m1r = -INFINITY, l0r = 0.f, l1r = 0.f;
    const float scale = 0.125f;

    const int brow = (lane & 7) + ((lane >> 4) << 3);
    const int bco  = ((lane >> 3) & 1) * 8;

    for (int k0 = 0; k0 < SS; k0 += 64) {
        __syncthreads();   // previous iteration's fragment loads complete

        // --- load K tile (hi/lo) ---
        #pragma unroll
        for (int i = 0; i < 16; i++) {
            int idx = t + i * 128;
            int r = idx >> 5, cu = idx & 31;
            size_t g = ((size_t)b * SS + k0 + r) * 32 + cu;
            *(uint32_t*)&Kh[r][cu * 2] = g_kh[g];
            *(uint32_t*)&Kl[r][cu * 2] = g_kl[g];
        }
        // --- load V tile transposed: Vh/Vl[d][key] ---
        {
            size_t base = ((size_t)b * SS + k0 + 2 * lane) * 32 + warp * 8;
            uint32_t h0[8], h1[8], u0[8], u1[8];
            #pragma unroll
            for (int j = 0; j < 8; j++) {
                h0[j] = g_vh[base + j];      h1[j] = g_vh[base + 32 + j];
                u0[j] = g_vl[base + j];      u1[j] = g_vl[base + 32 + j];
            }
            #pragma unroll
            for (int dd = 0; dd < 16; dd++) {
                int j = dd >> 1;
                uint32_t ah = (dd & 1) ? (h0[j] >> 16) : (h0[j] & 0xffffu);
                uint32_t bh = (dd & 1) ? (h1[j] >> 16) : (h1[j] & 0xffffu);
                uint32_t al = (dd & 1) ? (u0[j] >> 16) : (u0[j] & 0xffffu);
                uint32_t bl = (dd & 1) ? (u1[j] >> 16) : (u1[j] & 0xffffu);
                *(uint32_t*)&Vh[warp * 16 + dd][2 * lane] = ah | (bh << 16);
                *(uint32_t*)&Vl[warp * 16 + dd][2 * lane] = al | (bl << 16);
            }
        }
        if (t < 64) ms[t] = mask[(size_t)b * SS + k0 + t] ? -INFINITY : 0.0f;
        __syncthreads();

        // --- S = Q K^T (bf16x3 split) ---
        float S[8][4] = {};
        #pragma unroll
        for (int ks = 0; ks < 4; ks++) {
            #pragma unroll
            for (int pr = 0; pr < 4; pr++) {   // 4 pairs of key-atoms = 8 atoms
                uint32_t bh0, bh1, bh2, bh3, bl0, bl1, bl2, bl3;
                ldsm_x4(smem_u32(&Kh[pr * 16 + brow][ks * 16 + bco]), bh0, bh1, bh2, bh3);
                ldsm_x4(smem_u32(&Kl[pr * 16 + brow][ks * 16 + bco]), bl0, bl1, bl2, bl3);
                float* s0 = S[pr * 2];
                float* s1 = S[pr * 2 + 1];
                mma_bf16(s0, qh[ks][0], qh[ks][1], qh[ks][2], qh[ks][3], bh0, bh1);
                mma_bf16(s0, qh[ks][0], qh[ks][1], qh[ks][2], qh[ks][3], bl0, bl1);
                mma_bf16(s0, ql[ks][0], ql[ks][1], ql[ks][2], ql[ks][3], bh0, bh1);
                mma_bf16(s1, qh[ks][0], qh[ks][1], qh[ks][2], qh[ks][3], bh2, bh3);
                mma_bf16(s1, qh[ks][0], qh[ks][1], qh[ks][2], qh[ks][3], bl2, bl3);
                mma_bf16(s1, ql[ks][0], ql[ks][1], ql[ks][2], ql[ks][3], bh2, bh3);
            }
        }

        // --- online softmax (rows lane/4 and lane/4+8; quad lanes share a row) ---
        float rmax0 = -INFINITY, rmax1 = -INFINITY;
        #pragma unroll
        for (int na = 0; na < 8; na++) {
            int col = na * 8 + (lane & 3) * 2;
            float ma = ms[col], mb = ms[col + 1];
            S[na][0] = S[na][0] * scale + ma;
            S[na][1] = S[na][1] * scale + mb;
            S[na][2] = S[na][2] * scale + ma;
            S[na][3] = S[na][3] * scale + mb;
            rmax0 = fmaxf(rmax0, fmaxf(S[na][0], S[na][1]));
            rmax1 = fmaxf(rmax1, fmaxf(S[na][2], S[na][3]));
        }
        rmax0 = fmaxf(rmax0, __shfl_xor_sync(0xffffffffu, rmax0, 1));
        rmax0 = fmaxf(rmax0, __shfl_xor_sync(0xffffffffu, rmax0, 2));
        rmax1 = fmaxf(rmax1, __shfl_xor_sync(0xffffffffu, rmax1, 1));
        rmax1 = fmaxf(rmax1, __shfl_xor_sync(0xffffffffu, rmax1, 2));

        float nm0 = fmaxf(m0r, rmax0), nm1 = fmaxf(m1r, rmax1);
        float f0 = (m0r == -INFINITY) ? 0.f : __expf(m0r - nm0);
        float f1 = (m1r == -INFINITY) ? 0.f : __expf(m1r - nm1);
        float rs0 = 0.f, rs1 = 0.f;
        #pragma unroll
        for (int na = 0; na < 8; na++) {
            float p0 = __expf(S[na][0] - nm0); p0 = (S[na][0] == -INFINITY) ? 0.f : p0;
            float p1 = __expf(S[na][1] - nm0); p1 = (S[na][1] == -INFINITY) ? 0.f : p1;
            float p2 = __expf(S[na][2] - nm1); p2 = (S[na][2] == -INFINITY) ? 0.f : p2;
            float p3 = __expf(S[na][3] - nm1); p3 = (S[na][3] == -INFINITY) ? 0.f : p3;
            S[na][0] = p0; S[na][1] = p1; S[na][2] = p2; S[na][3] = p3;
            rs0 += p0 + p1; rs1 += p2 + p3;
        }
        rs0 += __shfl_xor_sync(0xffffffffu, rs0, 1);
        rs0 += __shfl_xor_sync(0xffffffffu, rs0, 2);
        rs1 += __shfl_xor_sync(0xffffffffu, rs1, 1);
        rs1 += __shfl_xor_sync(0xffffffffu, rs1, 2);
        l0r = l0r * f0 + rs0;  m0r = nm0;
        l1r = l1r * f1 + rs1;  m1r = nm1;

        #pragma unroll
        for (int na = 0; na < 8; na++) {
            O[na][0] *= f0; O[na][1] *= f0;
            O[na][2] *= f1; O[na][3] *= f1;
        }

        // --- O += P V (P repacked from S regs; bf16x3 split) ---
        #pragma unroll
        for (int kk = 0; kk < 4; kk++) {
            uint32_t ph[4], pl[4];
            split_pair(S[2 * kk][0],     S[2 * kk][1],     ph[0], pl[0]);
            split_pair(S[2 * kk][2],     S[2 * kk][3],     ph[1], pl[1]);
            split_pair(S[2 * kk + 1][0], S[2 * kk + 1][1], ph[2], pl[2]);
            split_pair(S[2 * kk + 1][2], S[2 * kk + 1][3], ph[3], pl[3]);
            #pragma unroll
            for (int pr = 0; pr < 4; pr++) {   // 4 pairs of d-atoms = 8 atoms
                uint32_t bh0, bh1, bh2, bh3, bl0, bl1, bl2, bl3;
                ldsm_x4(smem_u32(&Vh[pr * 16 + brow][kk * 16 + bco]), bh0, bh1, bh2, bh3);
                ldsm_x4(smem_u32(&Vl[pr * 16 + brow][kk * 16 + bco]), bl0, bl1, bl2, bl3);
                float* o0 = O[pr * 2];
                float* o1 = O[pr * 2 + 1];
                mma_bf16(o0, ph[0], ph[1], ph[2], ph[3], bh0, bh1);
                mma_bf16(o0, ph[0], ph[1], ph[2], ph[3], bl0, bl1);
                mma_bf16(o0, pl[0], pl[1], pl[2], pl[3], bh0, bh1);
                mma_bf16(o1, ph[0], ph[1], ph[2], ph[3], bh2, bh3);
                mma_bf16(o1, ph[0], ph[1], ph[2], ph[3], bl2, bl3);
                mma_bf16(o1, pl[0], pl[1], pl[2], pl[3], bh2, bh3);
            }
        }
    }

    // --- epilogue ---
    float inv0 = 1.f / l0r, inv1 = 1.f / l1r;
    int row0 = q0 + warp * 16 + (lane >> 2);
    #pragma unroll
    for (int na = 0; na < 8; na++) {
        int col = na * 8 + (lane & 3) * 2;
        float2 v0 = make_float2(O[na][0] * inv0, O[na][1] * inv0);
        *(float2*)&out[((size_t)b * SS + row0) * DD + col] = v0;
        float2 v1 = make_float2(O[na][2] * inv1, O[na][3] * inv1);
        *(float2*)&out[((size_t)b * SS + row0 + 8) * DD + col] = v1;
    }
}

// ---------------------------------------------------------------------------
// Launch
// ---------------------------------------------------------------------------
extern "C" void kernel_launch(void* const* d_in, const int* in_sizes, int n_in,
                              void* d_out, int out_size) {
    const float* x  = (const float*)d_in[0];
    const float* Wq = (const float*)d_in[1];
    const float* bq = (const float*)d_in[2];
    const float* Wk = (const float*)d_in[3];
    const float* bk = (const float*)d_in[4];
    const float* Wv = (const float*)d_in[5];
    const float* bv = (const float*)d_in[6];
    const int*   pm = (const int*)d_in[7];
    float* out = (float*)d_out;

    qkv_kernel<<<BB * SS / 64, 256>>>(x, Wq, bq, Wk, bk, Wv, bv);
    attn_kernel<<<dim3(SS / 64, BB), 128>>>(pm, out);
}

// round 3
// speedup vs baseline: 3.1112x; 1.7181x over previous
#include <cuda_runtime.h>
#include <cstdint>
#include <math.h>

#define BB 8
#define SS 2048
#define EE 1024
#define DD 64
#define NT (SS / 64)

// q,k,v stored as bf16 hi/lo planes, 2 bf16 packed per u32 (even d in low half)
__device__ unsigned int g_qh[BB * SS * DD / 2];
__device__ unsigned int g_ql[BB * SS * DD / 2];
__device__ unsigned int g_kh[BB * SS * DD / 2];
__device__ unsigned int g_kl[BB * SS * DD / 2];
__device__ unsigned int g_vh[BB * SS * DD / 2];
__device__ unsigned int g_vl[BB * SS * DD / 2];

// ---------------------------------------------------------------------------
// helpers
// ---------------------------------------------------------------------------
__device__ __forceinline__ uint32_t smem_u32(const void* p) {
    return (uint32_t)__cvta_generic_to_shared(p);
}

__device__ __forceinline__ void ldsm_x4(uint32_t addr, uint32_t& r0, uint32_t& r1,
                                        uint32_t& r2, uint32_t& r3) {
    asm volatile("ldmatrix.sync.aligned.m8n8.x4.shared.b16 {%0,%1,%2,%3}, [%4];"
                 : "=r"(r0), "=r"(r1), "=r"(r2), "=r"(r3) : "r"(addr));
}

__device__ __forceinline__ void ldsm_x4_t(uint32_t addr, uint32_t& r0, uint32_t& r1,
                                          uint32_t& r2, uint32_t& r3) {
    asm volatile("ldmatrix.sync.aligned.m8n8.x4.trans.shared.b16 {%0,%1,%2,%3}, [%4];"
                 : "=r"(r0), "=r"(r1), "=r"(r2), "=r"(r3) : "r"(addr));
}

__device__ __forceinline__ void mma_bf16(float c[4],
                                         uint32_t a0, uint32_t a1, uint32_t a2, uint32_t a3,
                                         uint32_t b0, uint32_t b1) {
    asm volatile("mma.sync.aligned.m16n8k16.row.col.f32.bf16.bf16.f32 "
                 "{%0,%1,%2,%3}, {%4,%5,%6,%7}, {%8,%9}, {%0,%1,%2,%3};"
                 : "+f"(c[0]), "+f"(c[1]), "+f"(c[2]), "+f"(c[3])
                 : "r"(a0), "r"(a1), "r"(a2), "r"(a3), "r"(b0), "r"(b1));
}

__device__ __forceinline__ uint32_t pack2(float x0, float x1) {
    uint32_t h;
    asm("cvt.rn.bf16x2.f32 %0, %1, %2;" : "=r"(h) : "f"(x1), "f"(x0));
    return h;
}

__device__ __forceinline__ void split_pair(float x0, float x1, uint32_t& hi, uint32_t& lo) {
    hi = pack2(x0, x1);
    float h0 = __uint_as_float(hi << 16);
    float h1 = __uint_as_float(hi & 0xffff0000u);
    lo = pack2(x0 - h0, x1 - h1);
}

__device__ __forceinline__ void cp16(uint32_t s, const void* g) {
    asm volatile("cp.async.cg.shared.global [%0], [%1], 16;" :: "r"(s), "l"(g));
}

// ---------------------------------------------------------------------------
// QKV projection (M=16384, N=64, K=1024), bf16 hi/lo split, register-prefetch
// pipelined. 256 threads = 8 warps (4 along M x 2 along N). BM=64, BK=16.
// ---------------------------------------------------------------------------
#define AP 24
#define WP 24

__global__ __launch_bounds__(256) void qkv_kernel(
    const float* __restrict__ x,
    const float* __restrict__ Wq, const float* __restrict__ bq,
    const float* __restrict__ Wk, const float* __restrict__ bk,
    const float* __restrict__ Wv, const float* __restrict__ bv)
{
    __shared__ unsigned short Ah[64][AP], Al[64][AP];
    __shared__ unsigned short Wh[3][64][WP], Wl[3][64][WP];

    const int t = threadIdx.x;
    const int warp = t >> 5, lane = t & 31;
    const int wm = warp >> 1;
    const int wn = warp & 1;
    const int m0 = blockIdx.x * 64;

    float acc[3][4][4] = {};

    const int arow = wm * 16 + (lane & 15);
    const int acol = (lane >> 4) * 8;
    const int brow = (lane & 7) + ((lane >> 4) << 3);
    const int bcol = ((lane >> 3) & 1) * 8;

    const uint32_t a_addr_h = smem_u32(&Ah[arow][acol]);
    const uint32_t a_addr_l = smem_u32(&Al[arow][acol]);

    // loader mapping
    const int axr = (t * 4) >> 4, axc = (t * 4) & 15;   // x tile
    const int wr = t >> 2, wc = (t & 3) * 4;            // W tiles

    // prologue: load tile k0=0 into registers
    float4 xa = *reinterpret_cast<const float4*>(&x[(size_t)(m0 + axr) * EE + axc]);
    float4 wv0 = *reinterpret_cast<const float4*>(&Wq[(size_t)wr * EE + wc]);
    float4 wv1 = *reinterpret_cast<const float4*>(&Wk[(size_t)wr * EE + wc]);
    float4 wv2 = *reinterpret_cast<const float4*>(&Wv[(size_t)wr * EE + wc]);

    for (int k0 = 0; k0 < EE; k0 += 16) {
        // STS current registers (split to bf16 hi/lo)
        {
            uint32_t h0, l0, h1, l1;
            split_pair(xa.x, xa.y, h0, l0);
            split_pair(xa.z, xa.w, h1, l1);
            *(uint32_t*)&Ah[axr][axc]     = h0;  *(uint32_t*)&Al[axr][axc]     = l0;
            *(uint32_t*)&Ah[axr][axc + 2] = h1;  *(uint32_t*)&Al[axr][axc + 2] = l1;
            float4 ws[3] = {wv0, wv1, wv2};
            #pragma unroll
            for (int i = 0; i < 3; i++) {
                split_pair(ws[i].x, ws[i].y, h0, l0);
                split_pair(ws[i].z, ws[i].w, h1, l1);
                *(uint32_t*)&Wh[i][wr][wc]     = h0;  *(uint32_t*)&Wl[i][wr][wc]     = l0;
                *(uint32_t*)&Wh[i][wr][wc + 2] = h1;  *(uint32_t*)&Wl[i][wr][wc + 2] = l1;
            }
        }
        __syncthreads();

        // prefetch next tile (overlaps with MMAs below)
        if (k0 + 16 < EE) {
            int kn = k0 + 16;
            xa  = *reinterpret_cast<const float4*>(&x[(size_t)(m0 + axr) * EE + kn + axc]);
            wv0 = *reinterpret_cast<const float4*>(&Wq[(size_t)wr * EE + kn + wc]);
            wv1 = *reinterpret_cast<const float4*>(&Wk[(size_t)wr * EE + kn + wc]);
            wv2 = *reinterpret_cast<const float4*>(&Wv[(size_t)wr * EE + kn + wc]);
        }

        uint32_t ah[4], al[4];
        ldsm_x4(a_addr_h, ah[0], ah[1], ah[2], ah[3]);
        ldsm_x4(a_addr_l, al[0], al[1], al[2], al[3]);

        #pragma unroll
        for (int mat = 0; mat < 3; mat++) {
            #pragma unroll
            for (int pr = 0; pr < 2; pr++) {
                uint32_t bh0, bh1, bh2, bh3, bl0, bl1, bl2, bl3;
                ldsm_x4(smem_u32(&Wh[mat][wn * 32 + pr * 16 + brow][bcol]), bh0, bh1, bh2, bh3);
                ldsm_x4(smem_u32(&Wl[mat][wn * 32 + pr * 16 + brow][bcol]), bl0, bl1, bl2, bl3);
                float* c0 = acc[mat][pr * 2];
                float* c1 = acc[mat][pr * 2 + 1];
                mma_bf16(c0, ah[0], ah[1], ah[2], ah[3], bh0, bh1);
                mma_bf16(c0, ah[0], ah[1], ah[2], ah[3], bl0, bl1);
                mma_bf16(c0, al[0], al[1], al[2], al[3], bh0, bh1);
                mma_bf16(c1, ah[0], ah[1], ah[2], ah[3], bh2, bh3);
                mma_bf16(c1, ah[0], ah[1], ah[2], ah[3], bl2, bl3);
                mma_bf16(c1, al[0], al[1], al[2], al[3], bh2, bh3);
            }
        }
        __syncthreads();
    }

    #pragma unroll
    for (int mat = 0; mat < 3; mat++) {
        const float* bias = (mat == 0) ? bq : (mat == 1) ? bk : bv;
        unsigned int* gh = (mat == 0) ? g_qh : (mat == 1) ? g_kh : g_vh;
        unsigned int* gl = (mat == 0) ? g_ql : (mat == 1) ? g_kl : g_vl;
        #pragma unroll
        for (int na = 0; na < 4; na++) {
            int col  = wn * 32 + na * 8 + (lane & 3) * 2;
            int row0 = m0 + wm * 16 + (lane >> 2);
            float b0 = bias[col], b1 = bias[col + 1];
            float c0 = acc[mat][na][0] + b0, c1 = acc[mat][na][1] + b1;
            float c2 = acc[mat][na][2] + b0, c3 = acc[mat][na][3] + b1;
            uint32_t h, l;
            split_pair(c0, c1, h, l);
            gh[(size_t)row0 * 32 + col / 2] = h;
            gl[(size_t)row0 * 32 + col / 2] = l;
            split_pair(c2, c3, h, l);
            gh[(size_t)(row0 + 8) * 32 + col / 2] = h;
            gl[(size_t)(row0 + 8) * 32 + col / 2] = l;
        }
    }
}

// ---------------------------------------------------------------------------
// Flash attention. 128 threads (4 warps, 16 q rows each), q-tile 64, key-tile
// 64. cp.async double-buffered K/V staging; V consumed via ldmatrix.trans
// (row-major, no transpose pass). Online softmax in registers.
// ---------------------------------------------------------------------------
#define KP 72                       // smem pitch (bf16)
#define TILE_U16 (64 * KP)          // one 64x64 bf16 plane
#define STAGE_U16 (4 * TILE_U16)    // Kh,Kl,Vh,Vl
#define ATTN_SMEM_BYTES (2 * STAGE_U16 * 2 + 64 * 4)

// stage one key tile (4 planes) via cp.async: 16 x 16B per thread
__device__ __forceinline__ void stage_tile(uint32_t sbase, size_t gbase, int t) {
    #pragma unroll
    for (int i = 0; i < 4; i++) {
        int chunk = t + i * 128;            // 0..511
        int r = chunk >> 3, c = chunk & 7;
        uint32_t soff = (uint32_t)(r * KP + c * 8) * 2;
        size_t goff = (size_t)r * 32 + c * 4;
        cp16(sbase + soff,                     g_kh + gbase + goff);
        cp16(sbase + TILE_U16 * 2 + soff,      g_kl + gbase + goff);
        cp16(sbase + 2 * TILE_U16 * 2 + soff,  g_vh + gbase + goff);
        cp16(sbase + 3 * TILE_U16 * 2 + soff,  g_vl + gbase + goff);
    }
}

__global__ __launch_bounds__(128, 3) void attn_kernel(const int* __restrict__ mask,
                                                      float* __restrict__ out)
{
    extern __shared__ unsigned short sm[];
    float* ms = (float*)(sm + 2 * STAGE_U16);

    const int t = threadIdx.x, warp = t >> 5, lane = t & 31;
    const int b = blockIdx.y, q0 = blockIdx.x * 64;

    // --- stage Q tile into stage-0 Kh/Kl planes, extract fragments ---
    {
        uint32_t s0 = smem_u32(sm);
        size_t gq = ((size_t)b * SS + q0) * 32;
        #pragma unroll
        for (int i = 0; i < 4; i++) {
            int chunk = t + i * 128;
            int r = chunk >> 3, c = chunk & 7;
            uint32_t soff = (uint32_t)(r * KP + c * 8) * 2;
            size_t goff = (size_t)r * 32 + c * 4;
            cp16(s0 + soff,                g_qh + gq + goff);
            cp16(s0 + TILE_U16 * 2 + soff, g_ql + gq + goff);
        }
        asm volatile("cp.async.commit_group;");
        asm volatile("cp.async.wait_group 0;");
        __syncthreads();
    }

    uint32_t qh[4][4], ql[4][4];
    {
        const int arow = warp * 16 + (lane & 15);
        const int acol = (lane >> 4) * 8;
        #pragma unroll
        for (int ks = 0; ks < 4; ks++) {
            ldsm_x4(smem_u32(&sm[arow * KP + ks * 16 + acol]),
                    qh[ks][0], qh[ks][1], qh[ks][2], qh[ks][3]);
            ldsm_x4(smem_u32(&sm[TILE_U16 + arow * KP + ks * 16 + acol]),
                    ql[ks][0], ql[ks][1], ql[ks][2], ql[ks][3]);
        }
    }
    __syncthreads();   // done reading Q before cp.async overwrites stage 0

    // --- prefetch key tile 0 into stage 0; mask into register ---
    const uint32_t stage_addr[2] = { smem_u32(sm), smem_u32(sm + STAGE_U16) };
    stage_tile(stage_addr[0], ((size_t)b * SS) * 32, t);
    asm volatile("cp.async.commit_group;");
    float mreg = 0.f;
    if (t < 64) mreg = mask[(size_t)b * SS + t] ? -INFINITY : 0.f;

    float O[8][4] = {};
    float m0r = -INFINITY, m1r = -INFINITY, l0r = 0.f, l1r = 0.f;
    const float scale = 0.125f;

    const int brow = (lane & 7) + ((lane >> 4) << 3);
    const int bco  = ((lane >> 3) & 1) * 8;
    const int vrow = lane & 15;             // trans-ldmatrix k-row within chunk
    const int vco  = (lane >> 4) * 8;       // trans-ldmatrix d offset

    for (int it = 0; it < NT; ++it) {
        const int st = it & 1;
        const unsigned short* Kh = sm + st * STAGE_U16;
        const unsigned short* Kl = Kh + TILE_U16;
        const unsigned short* Vh = Kh + 2 * TILE_U16;
        const unsigned short* Vl = Kh + 3 * TILE_U16;

        if (it + 1 < NT) {
            stage_tile(stage_addr[st ^ 1], ((size_t)b * SS + (it + 1) * 64) * 32, t);
            asm volatile("cp.async.commit_group;");
        }
        if (t < 64) ms[t] = mreg;
        if (it + 1 < NT && t < 64)
            mreg = mask[(size_t)b * SS + (it + 1) * 64 + t] ? -INFINITY : 0.f;

        if (it + 1 < NT) asm volatile("cp.async.wait_group 1;");
        else             asm volatile("cp.async.wait_group 0;");
        __syncthreads();

        // --- S = Q K^T (bf16x3) ---
        float S[8][4] = {};
        #pragma unroll
        for (int ks = 0; ks < 4; ks++) {
            #pragma unroll
            for (int pr = 0; pr < 4; pr++) {
                uint32_t bh0, bh1, bh2, bh3, bl0, bl1, bl2, bl3;
                ldsm_x4(smem_u32(&Kh[(pr * 16 + brow) * KP + ks * 16 + bco]), bh0, bh1, bh2, bh3);
                ldsm_x4(smem_u32(&Kl[(pr * 16 + brow) * KP + ks * 16 + bco]), bl0, bl1, bl2, bl3);
                float* s0 = S[pr * 2];
                float* s1 = S[pr * 2 + 1];
                mma_bf16(s0, qh[ks][0], qh[ks][1], qh[ks][2], qh[ks][3], bh0, bh1);
                mma_bf16(s0, qh[ks][0], qh[ks][1], qh[ks][2], qh[ks][3], bl0, bl1);
                mma_bf16(s0, ql[ks][0], ql[ks][1], ql[ks][2], ql[ks][3], bh0, bh1);
                mma_bf16(s1, qh[ks][0], qh[ks][1], qh[ks][2], qh[ks][3], bh2, bh3);
                mma_bf16(s1, qh[ks][0], qh[ks][1], qh[ks][2], qh[ks][3], bl2, bl3);
                mma_bf16(s1, ql[ks][0], ql[ks][1], ql[ks][2], ql[ks][3], bh2, bh3);
            }
        }

        // --- online softmax ---
        float rmax0 = -INFINITY, rmax1 = -INFINITY;
        #pragma unroll
        for (int na = 0; na < 8; na++) {
            int col = na * 8 + (lane & 3) * 2;
            float ma = ms[col], mb = ms[col + 1];
            S[na][0] = S[na][0] * scale + ma;
            S[na][1] = S[na][1] * scale + mb;
            S[na][2] = S[na][2] * scale + ma;
            S[na][3] = S[na][3] * scale + mb;
            rmax0 = fmaxf(rmax0, fmaxf(S[na][0], S[na][1]));
            rmax1 = fmaxf(rmax1, fmaxf(S[na][2], S[na][3]));
        }
        rmax0 = fmaxf(rmax0, __shfl_xor_sync(0xffffffffu, rmax0, 1));
        rmax0 = fmaxf(rmax0, __shfl_xor_sync(0xffffffffu, rmax0, 2));
        rmax1 = fmaxf(rmax1, __shfl_xor_sync(0xffffffffu, rmax1, 1));
        rmax1 = fmaxf(rmax1, __shfl_xor_sync(0xffffffffu, rmax1, 2));

        float nm0 = fmaxf(m0r, rmax0), nm1 = fmaxf(m1r, rmax1);
        float f0 = (m0r == -INFINITY) ? 0.f : __expf(m0r - nm0);
        float f1 = (m1r == -INFINITY) ? 0.f : __expf(m1r - nm1);
        float rs0 = 0.f, rs1 = 0.f;
        #pragma unroll
        for (int na = 0; na < 8; na++) {
            float p0 = __expf(S[na][0] - nm0); p0 = (S[na][0] == -INFINITY) ? 0.f : p0;
            float p1 = __expf(S[na][1] - nm0); p1 = (S[na][1] == -INFINITY) ? 0.f : p1;
            float p2 = __expf(S[na][2] - nm1); p2 = (S[na][2] == -INFINITY) ? 0.f : p2;
            float p3 = __expf(S[na][3] - nm1); p3 = (S[na][3] == -INFINITY) ? 0.f : p3;
            S[na][0] = p0; S[na][1] = p1; S[na][2] = p2; S[na][3] = p3;
            rs0 += p0 + p1; rs1 += p2 + p3;
        }
        rs0 += __shfl_xor_sync(0xffffffffu, rs0, 1);
        rs0 += __shfl_xor_sync(0xffffffffu, rs0, 2);
        rs1 += __shfl_xor_sync(0xffffffffu, rs1, 1);
        rs1 += __shfl_xor_sync(0xffffffffu, rs1, 2);
        l0r = l0r * f0 + rs0;  m0r = nm0;
        l1r = l1r * f1 + rs1;  m1r = nm1;

        #pragma unroll
        for (int na = 0; na < 8; na++) {
            O[na][0] *= f0; O[na][1] *= f0;
            O[na][2] *= f1; O[na][3] *= f1;
        }

        // --- O += P V : V row-major via ldmatrix.trans (bf16x3) ---
        #pragma unroll
        for (int kk = 0; kk < 4; kk++) {
            uint32_t ph[4], pl[4];
            split_pair(S[2 * kk][0],     S[2 * kk][1],     ph[0], pl[0]);
            split_pair(S[2 * kk][2],     S[2 * kk][3],     ph[1], pl[1]);
            split_pair(S[2 * kk + 1][0], S[2 * kk + 1][1], ph[2], pl[2]);
            split_pair(S[2 * kk + 1][2], S[2 * kk + 1][3], ph[3], pl[3]);
            #pragma unroll
            for (int pr = 0; pr < 4; pr++) {
                uint32_t bh0, bh1, bh2, bh3, bl0, bl1, bl2, bl3;
                ldsm_x4_t(smem_u32(&Vh[(kk * 16 + vrow) * KP + pr * 16 + vco]), bh0, bh1, bh2, bh3);
                ldsm_x4_t(smem_u32(&Vl[(kk * 16 + vrow) * KP + pr * 16 + vco]), bl0, bl1, bl2, bl3);
                float* o0 = O[pr * 2];
                float* o1 = O[pr * 2 + 1];
                mma_bf16(o0, ph[0], ph[1], ph[2], ph[3], bh0, bh1);
                mma_bf16(o0, ph[0], ph[1], ph[2], ph[3], bl0, bl1);
                mma_bf16(o0, pl[0], pl[1], pl[2], pl[3], bh0, bh1);
                mma_bf16(o1, ph[0], ph[1], ph[2], ph[3], bh2, bh3);
                mma_bf16(o1, ph[0], ph[1], ph[2], ph[3], bl2, bl3);
                mma_bf16(o1, pl[0], pl[1], pl[2], pl[3], bh2, bh3);
            }
        }
        __syncthreads();   // all warps done with this stage before overwrite
    }

    // --- epilogue ---
    float inv0 = 1.f / l0r, inv1 = 1.f / l1r;
    int row0 = q0 + warp * 16 + (lane >> 2);
    #pragma unroll
    for (int na = 0; na < 8; na++) {
        int col = na * 8 + (lane & 3) * 2;
        float2 v0 = make_float2(O[na][0] * inv0, O[na][1] * inv0);
        *(float2*)&out[((size_t)b * SS + row0) * DD + col] = v0;
        float2 v1 = make_float2(O[na][2] * inv1, O[na][3] * inv1);
        *(float2*)&out[((size_t)b * SS + row0 + 8) * DD + col] = v1;
    }
}

// ---------------------------------------------------------------------------
// Launch
// ---------------------------------------------------------------------------
extern "C" void kernel_launch(void* const* d_in, const int* in_sizes, int n_in,
                              void* d_out, int out_size) {
    const float* x  = (const float*)d_in[0];
    const float* Wq = (const float*)d_in[1];
    const float* bq = (const float*)d_in[2];
    const float* Wk = (const float*)d_in[3];
    const float* bk = (const float*)d_in[4];
    const float* Wv = (const float*)d_in[5];
    const float* bv = (const float*)d_in[6];
    const int*   pm = (const int*)d_in[7];
    float* out = (float*)d_out;

    qkv_kernel<<<BB * SS / 64, 256>>>(x, Wq, bq, Wk, bk, Wv, bv);

    cudaFuncSetAttribute(attn_kernel, cudaFuncAttributeMaxDynamicSharedMemorySize,
                         ATTN_SMEM_BYTES);
    attn_kernel<<<dim3(SS / 64, BB), 128, ATTN_SMEM_BYTES>>>(pm, out);
}